// round 3
// baseline (speedup 1.0000x reference)
#include <cuda_runtime.h>
#include <math.h>
#include <stdint.h>

#define NPOS 2500
#define NPAD 2560
#define NANCH 22500
#define PRE 6000
#define POST 300
#define CAP 8192
#define KSPLIT 6
#define KPART 768          // 4608 / 6
#define NW 94              // 6000 bits -> 94 u64 words
#define MW 96              // padded row stride in words

typedef unsigned long long ull;

// ---------------- scratch ----------------
__device__ float g_wt[4608 * 512];              // transposed weights [K][M]
__device__ float g_col[4608 * NPAD];            // im2col matrix [4608][2560]
__device__ float g_part[KSPLIT][512 * NPAD];    // split-K partials
__device__ float g_feat[512 * NPAD];            // conv output (bias+leaky)
__device__ float4 g_boxes[NANCH];
__device__ unsigned int g_key32[NANCH];
__device__ unsigned int g_hist[65536];
__device__ unsigned int g_cut;
__device__ unsigned int g_cnt;
__device__ ull g_sel[CAP];
__device__ float4 g_sbox[PRE];                  // boxes in rank order
__device__ ull g_mask[(size_t)PRE * MW];        // suppression bitmask matrix

// ---------------- f32x2 helpers ----------------
__device__ __forceinline__ void fma2(ull& d, ull a, ull b) {
    asm("fma.rn.f32x2 %0, %1, %2, %0;" : "+l"(d) : "l"(a), "l"(b));
}
__device__ __forceinline__ ull splat2(float x) {
    ull r;
    unsigned u = __float_as_uint(x);
    asm("mov.b64 %0, {%1, %1};" : "=l"(r) : "r"(u));
    return r;
}

// ---------------- zero histogram ----------------
__global__ void zero_hist_kernel() {
    g_hist[blockIdx.x * 256 + threadIdx.x] = 0u;
}

// ---------------- weight transpose: Wt[k][m] = W[m][k] ----------------
__global__ __launch_bounds__(256) void wt_kernel(const float* __restrict__ W) {
    __shared__ float sm[32][33];
    int k0 = blockIdx.x * 32;
    int m0 = blockIdx.y * 32;
    int tx = threadIdx.x & 31;
    int ty = threadIdx.x >> 5;     // 0..7
#pragma unroll
    for (int i = 0; i < 4; i++)
        sm[ty + i * 8][tx] = W[(size_t)(m0 + ty + i * 8) * 4608 + k0 + tx];
    __syncthreads();
#pragma unroll
    for (int i = 0; i < 4; i++)
        g_wt[(size_t)(k0 + ty + i * 8) * 512 + m0 + tx] = sm[tx][ty + i * 8];
}

// ---------------- im2col: g_col[k][n] ----------------
__global__ __launch_bounds__(256) void im2col_kernel(const float* __restrict__ in) {
    int n = blockIdx.x * 256 + threadIdx.x;     // 0..2559
    int k = blockIdx.y;                          // 0..4607
    if (n >= NPAD) return;
    float v = 0.f;
    if (n < NPOS) {
        int ci = k / 9;
        int r = k - ci * 9;
        int kh = r / 3;
        int kw = r - kh * 3;
        int h = n / 50;
        int w = n - h * 50;
        int ih = h + kh - 1;
        int iw = w + kw - 1;
        if (ih >= 0 && ih < 50 && iw >= 0 && iw < 50)
            v = in[ci * NPOS + ih * 50 + iw];
    }
    g_col[(size_t)k * NPAD + n] = v;
}

// ---------------- conv GEMM: split-K, 128x64 tiles, f32x2, coalesced A ----------------
// grid (40, 4, 6), 128 threads. thread tile 8(M) x 8(N) -> 8 x 4 f32x2 accs.
__global__ __launch_bounds__(128) void conv_gemm_kernel() {
    __shared__ float As[2][16][128];
    __shared__ float Bs[2][16][64];
    const int bn = blockIdx.x * 64;
    const int bm = blockIdx.y * 128;
    const int kb = blockIdx.z * KPART;
    const int t = threadIdx.x;
    const int tm = t >> 3;    // 0..15
    const int tn = t & 7;     // 0..7

    ull acc[8][4];
#pragma unroll
    for (int i = 0; i < 8; i++)
#pragma unroll
        for (int j = 0; j < 4; j++) acc[i][j] = 0ull;

    // A load mapping: p in 0..3, q = t + 128p -> row q>>5, col (q&31)*4
    int akl[4], amc[4];
#pragma unroll
    for (int p = 0; p < 4; p++) {
        int q = t + 128 * p;
        akl[p] = q >> 5;
        amc[p] = (q & 31) * 4;
    }
    // B load mapping: p in 0..1, q = t + 128p -> row q>>4, col (q&15)*4
    int bkl[2], bnc[2];
#pragma unroll
    for (int p = 0; p < 2; p++) {
        int q = t + 128 * p;
        bkl[p] = q >> 4;
        bnc[p] = (q & 15) * 4;
    }

    float4 ar[4], br[2];
    // prologue: tile 0
#pragma unroll
    for (int p = 0; p < 4; p++)
        ar[p] = *(const float4*)&g_wt[(size_t)(kb + akl[p]) * 512 + bm + amc[p]];
#pragma unroll
    for (int p = 0; p < 2; p++)
        br[p] = *(const float4*)&g_col[(size_t)(kb + bkl[p]) * NPAD + bn + bnc[p]];
#pragma unroll
    for (int p = 0; p < 4; p++)
        *(float4*)&As[0][akl[p]][amc[p]] = ar[p];
#pragma unroll
    for (int p = 0; p < 2; p++)
        *(float4*)&Bs[0][bkl[p]][bnc[p]] = br[p];
    __syncthreads();

    int cur = 0;
    for (int it = 0; it < KPART / 16; it++) {
        int nxt = cur ^ 1;
        bool more = (it + 1) < KPART / 16;
        if (more) {
            int k0 = kb + (it + 1) * 16;
#pragma unroll
            for (int p = 0; p < 4; p++)
                ar[p] = *(const float4*)&g_wt[(size_t)(k0 + akl[p]) * 512 + bm + amc[p]];
#pragma unroll
            for (int p = 0; p < 2; p++)
                br[p] = *(const float4*)&g_col[(size_t)(k0 + bkl[p]) * NPAD + bn + bnc[p]];
        }
#pragma unroll
        for (int kk = 0; kk < 16; kk++) {
            float4 af0 = *(const float4*)&As[cur][kk][tm * 8];
            float4 af1 = *(const float4*)&As[cur][kk][tm * 8 + 4];
            ull bb0 = *(const ull*)&Bs[cur][kk][tn * 8];
            ull bb1 = *(const ull*)&Bs[cur][kk][tn * 8 + 2];
            ull bb2 = *(const ull*)&Bs[cur][kk][tn * 8 + 4];
            ull bb3 = *(const ull*)&Bs[cur][kk][tn * 8 + 6];
            ull aa[8];
            aa[0] = splat2(af0.x); aa[1] = splat2(af0.y);
            aa[2] = splat2(af0.z); aa[3] = splat2(af0.w);
            aa[4] = splat2(af1.x); aa[5] = splat2(af1.y);
            aa[6] = splat2(af1.z); aa[7] = splat2(af1.w);
#pragma unroll
            for (int i = 0; i < 8; i++) {
                fma2(acc[i][0], aa[i], bb0);
                fma2(acc[i][1], aa[i], bb1);
                fma2(acc[i][2], aa[i], bb2);
                fma2(acc[i][3], aa[i], bb3);
            }
        }
        if (more) {
#pragma unroll
            for (int p = 0; p < 4; p++)
                *(float4*)&As[nxt][akl[p]][amc[p]] = ar[p];
#pragma unroll
            for (int p = 0; p < 2; p++)
                *(float4*)&Bs[nxt][bkl[p]][bnc[p]] = br[p];
        }
        __syncthreads();
        cur = nxt;
    }

    float* dst = &g_part[blockIdx.z][(size_t)(bm + tm * 8) * NPAD + bn + tn * 8];
#pragma unroll
    for (int i = 0; i < 8; i++) {
        *(ull*)&dst[(size_t)i * NPAD]     = acc[i][0];
        *(ull*)&dst[(size_t)i * NPAD + 2] = acc[i][1];
        *(ull*)&dst[(size_t)i * NPAD + 4] = acc[i][2];
        *(ull*)&dst[(size_t)i * NPAD + 6] = acc[i][3];
    }
}

// ---------------- reduce split-K + bias + leaky ----------------
__global__ __launch_bounds__(256) void reduce_kernel(const float* __restrict__ bias) {
    int n = blockIdx.x * 256 + threadIdx.x;
    int m = blockIdx.y;
    size_t off = (size_t)m * NPAD + n;
    float v = g_part[0][off];
    v += g_part[1][off];
    v += g_part[2][off];
    v += g_part[3][off];
    v += g_part[4][off];
    v += g_part[5][off];
    v += bias[m];
    g_feat[off] = (v >= 0.f) ? v : 0.01f * v;
}

// ---------------- head GEMM (54x2560x512) fused with decode ----------------
__global__ __launch_bounds__(256) void head_decode_kernel(const float* __restrict__ reg_w,
                                                          const float* __restrict__ cls_w,
                                                          const float* __restrict__ reg_b,
                                                          const float* __restrict__ cls_b) {
    __shared__ float As[16][64];
    __shared__ float Bs[16][64];
    __shared__ float Psm[54][65];
    const int bn = blockIdx.x * 64;
    const int t = threadIdx.x;
    float acc[4][4];
#pragma unroll
    for (int i = 0; i < 4; i++)
#pragma unroll
        for (int j = 0; j < 4; j++) acc[i][j] = 0.f;

    const int tm = t >> 4, tn = t & 15;

    for (int k0 = 0; k0 < 512; k0 += 16) {
        {
            int m = t >> 2;
            int kq = (t & 3) * 4;
            float4 v = make_float4(0.f, 0.f, 0.f, 0.f);
            if (m < 36) v = *(const float4*)&reg_w[m * 512 + k0 + kq];
            else if (m < 54) v = *(const float4*)&cls_w[(m - 36) * 512 + k0 + kq];
            As[kq + 0][m] = v.x;
            As[kq + 1][m] = v.y;
            As[kq + 2][m] = v.z;
            As[kq + 3][m] = v.w;
        }
        {
            int kl = t >> 4;
            int nq = (t & 15) * 4;
            *(float4*)&Bs[kl][nq] = *(const float4*)&g_feat[(size_t)(k0 + kl) * NPAD + bn + nq];
        }
        __syncthreads();
#pragma unroll
        for (int kk = 0; kk < 16; kk++) {
            float a[4], b[4];
            *(float4*)&a[0] = *(float4*)&As[kk][tm * 4];
            *(float4*)&b[0] = *(float4*)&Bs[kk][tn * 4];
#pragma unroll
            for (int i = 0; i < 4; i++)
#pragma unroll
                for (int j = 0; j < 4; j++) acc[i][j] += a[i] * b[j];
        }
        __syncthreads();
    }
#pragma unroll
    for (int i = 0; i < 4; i++) {
        int m = tm * 4 + i;
        if (m < 54)
#pragma unroll
            for (int j = 0; j < 4; j++) Psm[m][tn * 4 + j] = acc[i][j];
    }
    __syncthreads();

    for (int c = t; c < 576; c += 256) {
        int pl = c / 9;
        int a = c - pl * 9;
        int pos = bn + pl;
        if (pos >= NPOS) continue;
        int h = pos / 50;
        int w = pos - h * 50;

        float pr0 = Psm[4 * a + 0][pl] + reg_b[4 * a + 0];
        float pr1 = Psm[4 * a + 1][pl] + reg_b[4 * a + 1];
        float pr2 = Psm[4 * a + 2][pl] + reg_b[4 * a + 2];
        float pr3 = Psm[4 * a + 3][pl] + reg_b[4 * a + 3];
        float l0 = Psm[36 + 2 * a + 0][pl] + cls_b[2 * a + 0];
        float l1 = Psm[36 + 2 * a + 1][pl] + cls_b[2 * a + 1];

        float mx = fmaxf(l0, l1);
        float e0 = expf(l0 - mx);
        float e1 = expf(l1 - mx);
        float score = e1 / (e0 + e1);

        const float rs_[3] = {0.5f, 1.0f, 2.0f};
        const float ss_[3] = {8.0f, 16.0f, 32.0f};
        int ri = a / 3;
        int si = a - ri * 3;
        float hs = (16.0f * ss_[si]) * sqrtf(rs_[ri]);
        float ws = (16.0f * ss_[si]) * sqrtf(1.0f / rs_[ri]);
        float cx = 16.0f * (float)h + 8.0f;
        float cy = 16.0f * (float)w + 8.0f;
        float ax1 = cx - ws * 0.5f;
        float ay1 = cy - hs * 0.5f;

        const float hi = 799.0f;
        float rx1 = fminf(fmaxf(pr0 + ax1, 0.f), hi);
        float ry1 = fminf(fmaxf(pr1 + ay1, 0.f), hi);
        float rx2 = fminf(fmaxf(pr0 + ax1 + pr2 + ws, 0.f), hi);
        float ry2 = fminf(fmaxf(pr1 + ay1 + pr3 + hs, 0.f), hi);

        float wv = pr2 + ws;
        float hv = pr3 + hs;
        bool valid = (wv >= 16.0f) && (hv >= 16.0f);
        float s = valid ? score : -INFINITY;

        int idx = pos * 9 + a;
        g_boxes[idx] = make_float4(rx1, ry1, rx2, ry2);

        unsigned u = __float_as_uint(s);
        u = (u & 0x80000000u) ? ~u : (u | 0x80000000u);
        unsigned du = ~u;
        g_key32[idx] = du;
        atomicAdd(&g_hist[du >> 16], 1u);
    }
}

// ---------------- select cutoff bin ----------------
__global__ __launch_bounds__(1024) void select_kernel() {
    __shared__ unsigned int ps[1024];
    const int t = threadIdx.x;
    unsigned int s = 0;
    int base = t * 64;
#pragma unroll 8
    for (int b = 0; b < 64; b++) s += g_hist[base + b];
    ps[t] = s;
    __syncthreads();
    for (int off = 1; off < 1024; off <<= 1) {
        unsigned int v = (t >= off) ? ps[t - off] : 0u;
        __syncthreads();
        ps[t] += v;
        __syncthreads();
    }
    unsigned int excl = ps[t] - s;
    if (excl < PRE && ps[t] >= PRE) {
        unsigned int c = excl;
        for (int b = 0; b < 64; b++) {
            c += g_hist[base + b];
            if (c >= PRE) { g_cut = (unsigned)(base + b); break; }
        }
    }
    if (t == 0) g_cnt = 0u;
    for (int i = t; i < CAP; i += 1024) g_sel[i] = 0xFFFFFFFFFFFFFFFFull;
}

// ---------------- compact ----------------
__global__ __launch_bounds__(256) void compact_kernel() {
    int i = blockIdx.x * 256 + threadIdx.x;
    if (i >= NANCH) return;
    unsigned int k = g_key32[i];
    if ((k >> 16) <= g_cut) {
        unsigned int p = atomicAdd(&g_cnt, 1u);
        if (p < CAP) g_sel[p] = ((ull)k << 32) | (unsigned)i;
    }
}

// ---------------- bitonic sort (multi-block, 8192 keys) ----------------
__device__ __forceinline__ void cmpswap_u64(ull* a, ull* b, bool up) {
    ull x = *a, y = *b;
    bool sw = up ? (x > y) : (x < y);
    if (sw) { *a = y; *b = x; }
}

__global__ __launch_bounds__(1024) void sort_local_kernel() {
    __shared__ ull s[2048];
    int base = blockIdx.x * 2048;
    int t = threadIdx.x;
    s[t] = g_sel[base + t];
    s[t + 1024] = g_sel[base + t + 1024];
    __syncthreads();
    for (int k = 2; k <= 2048; k <<= 1) {
        for (int j = k >> 1; j > 0; j >>= 1) {
            int i = ((t & ~(j - 1)) << 1) | (t & (j - 1));
            int p = i | j;
            bool up = (((base + i) & k) == 0);
            cmpswap_u64(&s[i], &s[p], up);
            __syncthreads();
        }
    }
    g_sel[base + t] = s[t];
    g_sel[base + t + 1024] = s[t + 1024];
}

__global__ __launch_bounds__(1024) void sort_pass_kernel(int k, int j) {
    int t = blockIdx.x * 1024 + threadIdx.x;   // CAP/2 threads
    int i = ((t & ~(j - 1)) << 1) | (t & (j - 1));
    int p = i + j;
    bool up = ((i & k) == 0);
    ull a = g_sel[i], b = g_sel[p];
    bool sw = up ? (a > b) : (a < b);
    if (sw) { g_sel[i] = b; g_sel[p] = a; }
}

__global__ __launch_bounds__(1024) void sort_low_kernel(int k) {
    __shared__ ull s[2048];
    int base = blockIdx.x * 2048;
    int t = threadIdx.x;
    s[t] = g_sel[base + t];
    s[t + 1024] = g_sel[base + t + 1024];
    __syncthreads();
    for (int j = 1024; j > 0; j >>= 1) {
        int i = ((t & ~(j - 1)) << 1) | (t & (j - 1));
        int p = i | j;
        bool up = (((base + i) & k) == 0);
        cmpswap_u64(&s[i], &s[p], up);
        __syncthreads();
    }
    g_sel[base + t] = s[t];
    g_sel[base + t + 1024] = s[t + 1024];
}

// ---------------- prep: boxes in rank order ----------------
__global__ void prep_kernel() {
    int r = blockIdx.x * 1024 + threadIdx.x;
    if (r < PRE) {
        int idx = (int)(g_sel[r] & 0xFFFFFFFFull);
        g_sbox[r] = g_boxes[idx];
    }
}

// ---------------- IoU bitmask matrix: g_mask[i][w] ----------------
// grid (47, 4): rows tile 128, cols tile 1536 (24 words)
__global__ __launch_bounds__(128) void mask_kernel() {
    int i = blockIdx.x * 128 + threadIdx.x;
    int c0 = blockIdx.y * 1536;
    if (i >= PRE) return;
    float4 bi = g_sbox[i];
    float ai = (bi.z - bi.x + 1.0f) * (bi.w - bi.y + 1.0f);
#pragma unroll 1
    for (int wb = 0; wb < 24; wb++) {
        int j0 = c0 + wb * 64;
        ull word = 0;
        if (j0 + 64 > i) {   // words entirely below diagonal stay 0 (harmless: those ranks already decided)
            int jend = min(j0 + 64, PRE);
            for (int j = j0; j < jend; j++) {
                float4 bj = g_sbox[j];
                float aj = (bj.z - bj.x + 1.0f) * (bj.w - bj.y + 1.0f);
                float xx1 = fmaxf(bi.x, bj.x);
                float yy1 = fmaxf(bi.y, bj.y);
                float xx2 = fminf(bi.z, bj.z);
                float yy2 = fmaxf(bi.w, bj.w);   // reference's maximum bug preserved
                float w = fmaxf(0.f, xx2 - xx1 + 1.0f);
                float h = fmaxf(0.f, yy2 - yy1 + 1.0f);
                float inter = w * h;
                float ov = inter / (ai + aj - inter);
                if (ov > 0.7f) word |= 1ull << (j - j0);
            }
        }
        g_mask[(size_t)i * MW + blockIdx.y * 24 + wb] = word;
    }
}

// ---------------- batched greedy NMS + output (1 block, 128 threads) ----------------
__global__ __launch_bounds__(128) void greedy_kernel(float* __restrict__ out) {
    __shared__ ull live[NW];
    __shared__ ull rows[32][MW];
    __shared__ ull kf[NW];
    __shared__ int cand[32];
    __shared__ int sel[POST];
    __shared__ int s_ncand, s_nsel, s_done;
    __shared__ unsigned s_keptm;
    const int t = threadIdx.x;

    for (int w = t; w < NW; w += 128) {
        live[w] = (w == NW - 1) ? ((1ull << 48) - 1ull) : ~0ull;   // 93*64 + 48 = 6000
        kf[w] = 0ull;
    }
    if (t == 0) { s_nsel = 0; s_done = 0; }
    __syncthreads();

    while (true) {
        if (t == 0) {
            int nc = 0;
            for (int w = 0; w < NW && nc < 32; w++) {
                ull word = live[w];
                while (word && nc < 32) {
                    int b = __ffsll(word) - 1;
                    cand[nc++] = w * 64 + b;
                    word &= word - 1;
                }
            }
            s_ncand = nc;
        }
        __syncthreads();
        int nc = s_ncand;
        if (nc == 0 || s_done) break;

        for (int i = t; i < nc * MW; i += 128) {
            int r = i / MW, w = i - r * MW;
            rows[r][w] = g_mask[(size_t)cand[r] * MW + w];
        }
        __syncthreads();

        if (t == 0) {
            unsigned suppm = 0, keptm = 0;
            int nsel = s_nsel;
            for (int b = 0; b < nc; b++) {
                if ((suppm >> b) & 1u) continue;
                sel[nsel++] = cand[b];
                keptm |= 1u << b;
                if (nsel == POST) { s_done = 1; break; }
                for (int c = b + 1; c < nc; c++) {
                    if ((suppm >> c) & 1u) continue;
                    int j = cand[c];
                    if ((rows[b][j >> 6] >> (j & 63)) & 1ull) suppm |= 1u << c;
                }
            }
            s_nsel = nsel;
            s_keptm = keptm;
            for (int b = 0; b < nc; b++) {
                int j = cand[b];
                live[j >> 6] &= ~(1ull << (j & 63));       // all candidates consumed
                if ((keptm >> b) & 1u) kf[j >> 6] |= 1ull << (j & 63);
            }
        }
        __syncthreads();
        unsigned keptm = s_keptm;
        if (t < NW) {
            ull acc = 0;
            unsigned m = keptm;
            while (m) {
                int b = __ffs(m) - 1;
                m &= m - 1;
                acc |= rows[b][t];
            }
            live[t] &= ~acc;
        }
        __syncthreads();
        if (s_done) break;
    }

    // pad with suppressed (ascending rank) if fewer than 300 kept
    if (t == 0 && s_nsel < POST) {
        int c = s_nsel;
        for (int j = 0; j < PRE && c < POST; j++)
            if (!((kf[j >> 6] >> (j & 63)) & 1ull)) sel[c++] = j;
        s_nsel = c;
    }
    __syncthreads();

    for (int r = t; r < POST; r += 128) {
        int rk = sel[r];
        float4 b = g_sbox[rk];
        out[r * 4 + 0] = b.x;
        out[r * 4 + 1] = b.y;
        out[r * 4 + 2] = b.z - b.x + 1.0f;
        out[r * 4 + 3] = b.w - b.y + 1.0f;
    }
}

// ---------------- launch ----------------
extern "C" void kernel_launch(void* const* d_in, const int* in_sizes, int n_in,
                              void* d_out, int out_size) {
    const float* in_features = (const float*)d_in[0];
    const float* conv_w = (const float*)d_in[1];
    const float* conv_b = (const float*)d_in[2];
    const float* reg_w = (const float*)d_in[3];
    const float* reg_b = (const float*)d_in[4];
    const float* cls_w = (const float*)d_in[5];
    const float* cls_b = (const float*)d_in[6];
    float* out = (float*)d_out;

    const float* in7 = in_features + (size_t)7 * 512 * NPOS;  // only batch -1 consumed

    zero_hist_kernel<<<256, 256>>>();
    wt_kernel<<<dim3(144, 16), 256>>>(conv_w);
    im2col_kernel<<<dim3(10, 4608), 256>>>(in7);
    conv_gemm_kernel<<<dim3(40, 4, KSPLIT), 128>>>();
    reduce_kernel<<<dim3(10, 512), 256>>>(conv_b);
    head_decode_kernel<<<40, 256>>>(reg_w, cls_w, reg_b, cls_b);
    select_kernel<<<1, 1024>>>();
    compact_kernel<<<88, 256>>>();

    sort_local_kernel<<<4, 1024>>>();
    sort_pass_kernel<<<4, 1024>>>(4096, 2048);
    sort_low_kernel<<<4, 1024>>>(4096);
    sort_pass_kernel<<<4, 1024>>>(8192, 4096);
    sort_pass_kernel<<<4, 1024>>>(8192, 2048);
    sort_low_kernel<<<4, 1024>>>(8192);

    prep_kernel<<<6, 1024>>>();
    mask_kernel<<<dim3(47, 4), 128>>>();
    greedy_kernel<<<1, 128>>>(out);
}

// round 4
// speedup vs baseline: 1.3390x; 1.3390x over previous
#include <cuda_runtime.h>
#include <math.h>
#include <stdint.h>

#define NPOS 2500
#define NPAD 2560
#define NANCH 22500
#define PRE 6000
#define POST 300
#define CAP 8192
#define KSPLIT 6
#define KPART 768          // 4608 / 6
#define LW 188             // 6000 bits -> 188 u32 words

typedef unsigned long long ull;

// ---------------- scratch ----------------
__device__ float g_wt[4608 * 512];              // transposed weights [K][M]
__device__ float g_col[4608 * NPAD];            // im2col matrix [4608][2560]
__device__ float g_part[KSPLIT][512 * NPAD];    // split-K partials
__device__ float g_feat[512 * NPAD];            // conv output (bias+leaky)
__device__ float4 g_boxes[NANCH];
__device__ unsigned int g_key32[NANCH];
__device__ unsigned int g_hist[65536];
__device__ unsigned int g_cut;
__device__ unsigned int g_cnt;
__device__ ull g_sel[CAP];
__device__ float4 g_sbox[PRE];                  // boxes in rank order

// ---------------- f32x2 helpers ----------------
__device__ __forceinline__ void fma2(ull& d, ull a, ull b) {
    asm("fma.rn.f32x2 %0, %1, %2, %0;" : "+l"(d) : "l"(a), "l"(b));
}
__device__ __forceinline__ ull splat2(float x) {
    ull r;
    unsigned u = __float_as_uint(x);
    asm("mov.b64 %0, {%1, %1};" : "=l"(r) : "r"(u));
    return r;
}

// ---------------- zero histogram ----------------
__global__ void zero_hist_kernel() {
    g_hist[blockIdx.x * 256 + threadIdx.x] = 0u;
}

// ---------------- weight transpose: Wt[k][m] = W[m][k] ----------------
__global__ __launch_bounds__(256) void wt_kernel(const float* __restrict__ W) {
    __shared__ float sm[32][33];
    int k0 = blockIdx.x * 32;
    int m0 = blockIdx.y * 32;
    int tx = threadIdx.x & 31;
    int ty = threadIdx.x >> 5;     // 0..7
#pragma unroll
    for (int i = 0; i < 4; i++)
        sm[ty + i * 8][tx] = W[(size_t)(m0 + ty + i * 8) * 4608 + k0 + tx];
    __syncthreads();
#pragma unroll
    for (int i = 0; i < 4; i++)
        g_wt[(size_t)(k0 + ty + i * 8) * 512 + m0 + tx] = sm[tx][ty + i * 8];
}

// ---------------- im2col: g_col[k][n] ----------------
__global__ __launch_bounds__(256) void im2col_kernel(const float* __restrict__ in) {
    int n = blockIdx.x * 256 + threadIdx.x;     // 0..2559
    int k = blockIdx.y;                          // 0..4607
    if (n >= NPAD) return;
    float v = 0.f;
    if (n < NPOS) {
        int ci = k / 9;
        int r = k - ci * 9;
        int kh = r / 3;
        int kw = r - kh * 3;
        int h = n / 50;
        int w = n - h * 50;
        int ih = h + kh - 1;
        int iw = w + kw - 1;
        if (ih >= 0 && ih < 50 && iw >= 0 && iw < 50)
            v = in[ci * NPOS + ih * 50 + iw];
    }
    g_col[(size_t)k * NPAD + n] = v;
}

// ---------------- conv GEMM: split-K, 128x128 tiles, 256 thr, f32x2 ----------------
__global__ __launch_bounds__(256, 2) void conv_gemm_kernel() {
    __shared__ float As[2][16][128];
    __shared__ ull Bs[2][16][64];       // 128 floats per k-row as 64 f32x2
    const int bn = blockIdx.x * 128;
    const int bm = blockIdx.y * 128;
    const int kb = blockIdx.z * KPART;
    const int t = threadIdx.x;
    const int tm = t >> 4;    // 0..15
    const int tn = t & 15;    // 0..15

    ull acc[8][4];
#pragma unroll
    for (int i = 0; i < 8; i++)
#pragma unroll
        for (int j = 0; j < 4; j++) acc[i][j] = 0ull;

    int lrow[2], lcol[2];
#pragma unroll
    for (int p = 0; p < 2; p++) {
        int q = t + 256 * p;
        lrow[p] = q >> 5;           // 0..15
        lcol[p] = (q & 31) * 4;     // 0..124
    }

    float4 ar[2], br[2];
#pragma unroll
    for (int p = 0; p < 2; p++) {
        ar[p] = *(const float4*)&g_wt[(size_t)(kb + lrow[p]) * 512 + bm + lcol[p]];
        br[p] = *(const float4*)&g_col[(size_t)(kb + lrow[p]) * NPAD + bn + lcol[p]];
    }
#pragma unroll
    for (int p = 0; p < 2; p++) {
        *(float4*)&As[0][lrow[p]][lcol[p]] = ar[p];
        *(ulonglong2*)&Bs[0][lrow[p]][lcol[p] >> 1] = *(ulonglong2*)&br[p];
    }
    __syncthreads();

    int cur = 0;
    for (int it = 0; it < KPART / 16; it++) {
        int nxt = cur ^ 1;
        bool more = (it + 1) < KPART / 16;
        if (more) {
            int k0 = kb + (it + 1) * 16;
#pragma unroll
            for (int p = 0; p < 2; p++) {
                ar[p] = *(const float4*)&g_wt[(size_t)(k0 + lrow[p]) * 512 + bm + lcol[p]];
                br[p] = *(const float4*)&g_col[(size_t)(k0 + lrow[p]) * NPAD + bn + lcol[p]];
            }
        }
#pragma unroll
        for (int kk = 0; kk < 16; kk++) {
            float4 af0 = *(const float4*)&As[cur][kk][tm * 8];
            float4 af1 = *(const float4*)&As[cur][kk][tm * 8 + 4];
            ulonglong2 b01 = *(const ulonglong2*)&Bs[cur][kk][tn * 4];
            ulonglong2 b23 = *(const ulonglong2*)&Bs[cur][kk][tn * 4 + 2];
            ull aa[8];
            aa[0] = splat2(af0.x); aa[1] = splat2(af0.y);
            aa[2] = splat2(af0.z); aa[3] = splat2(af0.w);
            aa[4] = splat2(af1.x); aa[5] = splat2(af1.y);
            aa[6] = splat2(af1.z); aa[7] = splat2(af1.w);
#pragma unroll
            for (int i = 0; i < 8; i++) {
                fma2(acc[i][0], aa[i], b01.x);
                fma2(acc[i][1], aa[i], b01.y);
                fma2(acc[i][2], aa[i], b23.x);
                fma2(acc[i][3], aa[i], b23.y);
            }
        }
        if (more) {
#pragma unroll
            for (int p = 0; p < 2; p++) {
                *(float4*)&As[nxt][lrow[p]][lcol[p]] = ar[p];
                *(ulonglong2*)&Bs[nxt][lrow[p]][lcol[p] >> 1] = *(ulonglong2*)&br[p];
            }
        }
        __syncthreads();
        cur = nxt;
    }

    float* dst = &g_part[blockIdx.z][(size_t)(bm + tm * 8) * NPAD + bn + tn * 8];
#pragma unroll
    for (int i = 0; i < 8; i++) {
        *(ull*)&dst[(size_t)i * NPAD]     = acc[i][0];
        *(ull*)&dst[(size_t)i * NPAD + 2] = acc[i][1];
        *(ull*)&dst[(size_t)i * NPAD + 4] = acc[i][2];
        *(ull*)&dst[(size_t)i * NPAD + 6] = acc[i][3];
    }
}

// ---------------- reduce split-K + bias + leaky ----------------
__global__ __launch_bounds__(256) void reduce_kernel(const float* __restrict__ bias) {
    int n = blockIdx.x * 256 + threadIdx.x;
    int m = blockIdx.y;
    size_t off = (size_t)m * NPAD + n;
    float v = g_part[0][off];
    v += g_part[1][off];
    v += g_part[2][off];
    v += g_part[3][off];
    v += g_part[4][off];
    v += g_part[5][off];
    v += bias[m];
    g_feat[off] = (v >= 0.f) ? v : 0.01f * v;
}

// ---------------- head GEMM (54x2560x512) fused with decode ----------------
__global__ __launch_bounds__(256) void head_decode_kernel(const float* __restrict__ reg_w,
                                                          const float* __restrict__ cls_w,
                                                          const float* __restrict__ reg_b,
                                                          const float* __restrict__ cls_b) {
    __shared__ float As[16][64];
    __shared__ float Bs[16][64];
    __shared__ float Psm[54][65];
    const int bn = blockIdx.x * 64;
    const int t = threadIdx.x;
    float acc[4][4];
#pragma unroll
    for (int i = 0; i < 4; i++)
#pragma unroll
        for (int j = 0; j < 4; j++) acc[i][j] = 0.f;

    const int tm = t >> 4, tn = t & 15;

    for (int k0 = 0; k0 < 512; k0 += 16) {
        {
            int m = t >> 2;
            int kq = (t & 3) * 4;
            float4 v = make_float4(0.f, 0.f, 0.f, 0.f);
            if (m < 36) v = *(const float4*)&reg_w[m * 512 + k0 + kq];
            else if (m < 54) v = *(const float4*)&cls_w[(m - 36) * 512 + k0 + kq];
            As[kq + 0][m] = v.x;
            As[kq + 1][m] = v.y;
            As[kq + 2][m] = v.z;
            As[kq + 3][m] = v.w;
        }
        {
            int kl = t >> 4;
            int nq = (t & 15) * 4;
            *(float4*)&Bs[kl][nq] = *(const float4*)&g_feat[(size_t)(k0 + kl) * NPAD + bn + nq];
        }
        __syncthreads();
#pragma unroll
        for (int kk = 0; kk < 16; kk++) {
            float a[4], b[4];
            *(float4*)&a[0] = *(float4*)&As[kk][tm * 4];
            *(float4*)&b[0] = *(float4*)&Bs[kk][tn * 4];
#pragma unroll
            for (int i = 0; i < 4; i++)
#pragma unroll
                for (int j = 0; j < 4; j++) acc[i][j] += a[i] * b[j];
        }
        __syncthreads();
    }
#pragma unroll
    for (int i = 0; i < 4; i++) {
        int m = tm * 4 + i;
        if (m < 54)
#pragma unroll
            for (int j = 0; j < 4; j++) Psm[m][tn * 4 + j] = acc[i][j];
    }
    __syncthreads();

    for (int c = t; c < 576; c += 256) {
        int pl = c / 9;
        int a = c - pl * 9;
        int pos = bn + pl;
        if (pos >= NPOS) continue;
        int h = pos / 50;
        int w = pos - h * 50;

        float pr0 = Psm[4 * a + 0][pl] + reg_b[4 * a + 0];
        float pr1 = Psm[4 * a + 1][pl] + reg_b[4 * a + 1];
        float pr2 = Psm[4 * a + 2][pl] + reg_b[4 * a + 2];
        float pr3 = Psm[4 * a + 3][pl] + reg_b[4 * a + 3];
        float l0 = Psm[36 + 2 * a + 0][pl] + cls_b[2 * a + 0];
        float l1 = Psm[36 + 2 * a + 1][pl] + cls_b[2 * a + 1];

        float mx = fmaxf(l0, l1);
        float e0 = expf(l0 - mx);
        float e1 = expf(l1 - mx);
        float score = e1 / (e0 + e1);

        const float rs_[3] = {0.5f, 1.0f, 2.0f};
        const float ss_[3] = {8.0f, 16.0f, 32.0f};
        int ri = a / 3;
        int si = a - ri * 3;
        float hs = (16.0f * ss_[si]) * sqrtf(rs_[ri]);
        float ws = (16.0f * ss_[si]) * sqrtf(1.0f / rs_[ri]);
        float cx = 16.0f * (float)h + 8.0f;
        float cy = 16.0f * (float)w + 8.0f;
        float ax1 = cx - ws * 0.5f;
        float ay1 = cy - hs * 0.5f;

        const float hi = 799.0f;
        float rx1 = fminf(fmaxf(pr0 + ax1, 0.f), hi);
        float ry1 = fminf(fmaxf(pr1 + ay1, 0.f), hi);
        float rx2 = fminf(fmaxf(pr0 + ax1 + pr2 + ws, 0.f), hi);
        float ry2 = fminf(fmaxf(pr1 + ay1 + pr3 + hs, 0.f), hi);

        float wv = pr2 + ws;
        float hv = pr3 + hs;
        bool valid = (wv >= 16.0f) && (hv >= 16.0f);
        float s = valid ? score : -INFINITY;

        int idx = pos * 9 + a;
        g_boxes[idx] = make_float4(rx1, ry1, rx2, ry2);

        unsigned u = __float_as_uint(s);
        u = (u & 0x80000000u) ? ~u : (u | 0x80000000u);
        unsigned du = ~u;
        g_key32[idx] = du;
        atomicAdd(&g_hist[du >> 16], 1u);
    }
}

// ---------------- select cutoff bin ----------------
__global__ __launch_bounds__(1024) void select_kernel() {
    __shared__ unsigned int ps[1024];
    const int t = threadIdx.x;
    unsigned int s = 0;
    int base = t * 64;
#pragma unroll 8
    for (int b = 0; b < 64; b++) s += g_hist[base + b];
    ps[t] = s;
    __syncthreads();
    for (int off = 1; off < 1024; off <<= 1) {
        unsigned int v = (t >= off) ? ps[t - off] : 0u;
        __syncthreads();
        ps[t] += v;
        __syncthreads();
    }
    unsigned int excl = ps[t] - s;
    if (excl < PRE && ps[t] >= PRE) {
        unsigned int c = excl;
        for (int b = 0; b < 64; b++) {
            c += g_hist[base + b];
            if (c >= PRE) { g_cut = (unsigned)(base + b); break; }
        }
    }
    if (t == 0) g_cnt = 0u;
    for (int i = t; i < CAP; i += 1024) g_sel[i] = 0xFFFFFFFFFFFFFFFFull;
}

// ---------------- compact ----------------
__global__ __launch_bounds__(256) void compact_kernel() {
    int i = blockIdx.x * 256 + threadIdx.x;
    if (i >= NANCH) return;
    unsigned int k = g_key32[i];
    if ((k >> 16) <= g_cut) {
        unsigned int p = atomicAdd(&g_cnt, 1u);
        if (p < CAP) g_sel[p] = ((ull)k << 32) | (unsigned)i;
    }
}

// ---------------- bitonic sort (multi-block, 8192 keys) ----------------
__device__ __forceinline__ void cmpswap_u64(ull* a, ull* b, bool up) {
    ull x = *a, y = *b;
    bool sw = up ? (x > y) : (x < y);
    if (sw) { *a = y; *b = x; }
}

__global__ __launch_bounds__(1024) void sort_local_kernel() {
    __shared__ ull s[2048];
    int base = blockIdx.x * 2048;
    int t = threadIdx.x;
    s[t] = g_sel[base + t];
    s[t + 1024] = g_sel[base + t + 1024];
    __syncthreads();
    for (int k = 2; k <= 2048; k <<= 1) {
        for (int j = k >> 1; j > 0; j >>= 1) {
            int i = ((t & ~(j - 1)) << 1) | (t & (j - 1));
            int p = i | j;
            bool up = (((base + i) & k) == 0);
            cmpswap_u64(&s[i], &s[p], up);
            __syncthreads();
        }
    }
    g_sel[base + t] = s[t];
    g_sel[base + t + 1024] = s[t + 1024];
}

__global__ __launch_bounds__(1024) void sort_pass_kernel(int k, int j) {
    int t = blockIdx.x * 1024 + threadIdx.x;
    int i = ((t & ~(j - 1)) << 1) | (t & (j - 1));
    int p = i + j;
    bool up = ((i & k) == 0);
    ull a = g_sel[i], b = g_sel[p];
    bool sw = up ? (a > b) : (a < b);
    if (sw) { g_sel[i] = b; g_sel[p] = a; }
}

__global__ __launch_bounds__(1024) void sort_low_kernel(int k) {
    __shared__ ull s[2048];
    int base = blockIdx.x * 2048;
    int t = threadIdx.x;
    s[t] = g_sel[base + t];
    s[t + 1024] = g_sel[base + t + 1024];
    __syncthreads();
    for (int j = 1024; j > 0; j >>= 1) {
        int i = ((t & ~(j - 1)) << 1) | (t & (j - 1));
        int p = i | j;
        bool up = (((base + i) & k) == 0);
        cmpswap_u64(&s[i], &s[p], up);
        __syncthreads();
    }
    g_sel[base + t] = s[t];
    g_sel[base + t + 1024] = s[t + 1024];
}

// ---------------- prep: boxes in rank order ----------------
__global__ void prep_kernel() {
    int r = blockIdx.x * 1024 + threadIdx.x;
    if (r < PRE) {
        int idx = (int)(g_sel[r] & 0xFFFFFFFFull);
        g_sbox[r] = g_boxes[idx];
    }
}

// ---------------- NMS: single block, live bitmask + ballot suppression ----------------
extern __shared__ float nsm[];
__global__ __launch_bounds__(1024) void nms_kernel(float* __restrict__ out) {
    float* X1 = nsm;
    float* Y1 = X1 + PRE;
    float* X2 = Y1 + PRE;
    float* Y2 = X2 + PRE;
    float* AR = Y2 + PRE;
    unsigned char* keep = (unsigned char*)(AR + PRE);          // PRE bytes
    int* sel = (int*)((char*)nsm + 5 * PRE * 4 + 6016);        // POST ints
    __shared__ unsigned live[LW];
    __shared__ unsigned sup[LW];
    __shared__ int s_cur, s_nsel, s_wpos;
    const int t = threadIdx.x;

    for (int r = t; r < PRE; r += 1024) {
        float4 b = g_sbox[r];
        X1[r] = b.x; Y1[r] = b.y; X2[r] = b.z; Y2[r] = b.w;
        AR[r] = (b.z - b.x + 1.0f) * (b.w - b.y + 1.0f);
        keep[r] = 1;
    }
    if (t < LW) live[t] = (t == LW - 1) ? 0x0000FFFFu : 0xFFFFFFFFu;  // 187*32+16 = 6000
    if (t == 0) { s_nsel = 0; s_wpos = 0; }
    __syncthreads();

    while (true) {
        if (t == 0) {
            if (s_nsel >= POST) {
                s_cur = -1;
            } else {
                int w = s_wpos;
                unsigned word = 0;
                while (w < LW && (word = live[w]) == 0u) w++;
                s_wpos = w;
                if (w == LW) {
                    s_cur = -1;
                } else {
                    int b = __ffs(word) - 1;
                    int cur = w * 32 + b;
                    live[w] = word & ~(1u << b);
                    sel[s_nsel++] = cur;
                    s_cur = cur;
                }
            }
        }
        __syncthreads();
        int cur = s_cur;
        if (cur < 0) break;

        float x1i = X1[cur], y1i = Y1[cur], x2i = X2[cur], y2i = Y2[cur], ai = AR[cur];
        for (int jb0 = cur + 1; jb0 < PRE; jb0 += 1024) {
            int j = jb0 + t;
            bool supp = false;
            if (j < PRE) {
                float xx1 = fmaxf(x1i, X1[j]);
                float yy1 = fmaxf(y1i, Y1[j]);
                float xx2 = fminf(x2i, X2[j]);
                float yy2 = fmaxf(y2i, Y2[j]);   // reference's maximum bug preserved
                float w = fmaxf(0.f, xx2 - xx1 + 1.0f);
                float h = fmaxf(0.f, yy2 - yy1 + 1.0f);
                float inter = w * h;
                float ov = inter / (ai + AR[j] - inter);
                supp = (ov > 0.7f);
            }
            unsigned m = __ballot_sync(0xFFFFFFFFu, supp);
            if (supp) keep[j] = 0;
            if ((t & 31) == 0 && m) {
                int jb = jb0 + (t & ~31);        // j of lane 0
                int w0 = jb >> 5;
                int sh = jb & 31;
                atomicAnd(&live[w0], ~(m << sh));
                if (sh) {
                    unsigned hi2 = m >> (32 - sh);
                    if (hi2) atomicAnd(&live[w0 + 1], ~hi2);
                }
            }
        }
        __syncthreads();
    }

    // pad with suppressed (ascending rank): pack keep bytes into bitmask, then t0 extracts
    if (t < LW) {
        unsigned wsup = 0;
        int base = t * 32;
        for (int b = 0; b < 32; b++) {
            int j = base + b;
            if (j < PRE && !keep[j]) wsup |= 1u << b;
        }
        sup[t] = wsup;
    }
    __syncthreads();
    if (t == 0 && s_nsel < POST) {
        int c = s_nsel;
        for (int w = 0; w < LW && c < POST; w++) {
            unsigned word = sup[w];
            while (word && c < POST) {
                int b = __ffs(word) - 1;
                sel[c++] = w * 32 + b;
                word &= word - 1;
            }
        }
        s_nsel = c;
    }
    __syncthreads();

    if (t < POST) {
        int rk = sel[t];
        out[t * 4 + 0] = X1[rk];
        out[t * 4 + 1] = Y1[rk];
        out[t * 4 + 2] = X2[rk] - X1[rk] + 1.0f;
        out[t * 4 + 3] = Y2[rk] - Y1[rk] + 1.0f;
    }
}

// ---------------- launch ----------------
extern "C" void kernel_launch(void* const* d_in, const int* in_sizes, int n_in,
                              void* d_out, int out_size) {
    const float* in_features = (const float*)d_in[0];
    const float* conv_w = (const float*)d_in[1];
    const float* conv_b = (const float*)d_in[2];
    const float* reg_w = (const float*)d_in[3];
    const float* reg_b = (const float*)d_in[4];
    const float* cls_w = (const float*)d_in[5];
    const float* cls_b = (const float*)d_in[6];
    float* out = (float*)d_out;

    const float* in7 = in_features + (size_t)7 * 512 * NPOS;  // only batch -1 consumed

    zero_hist_kernel<<<256, 256>>>();
    wt_kernel<<<dim3(144, 16), 256>>>(conv_w);
    im2col_kernel<<<dim3(10, 4608), 256>>>(in7);
    conv_gemm_kernel<<<dim3(20, 4, KSPLIT), 256>>>();
    reduce_kernel<<<dim3(10, 512), 256>>>(conv_b);
    head_decode_kernel<<<40, 256>>>(reg_w, cls_w, reg_b, cls_b);
    select_kernel<<<1, 1024>>>();
    compact_kernel<<<88, 256>>>();

    sort_local_kernel<<<4, 1024>>>();
    sort_pass_kernel<<<4, 1024>>>(4096, 2048);
    sort_low_kernel<<<4, 1024>>>(4096);
    sort_pass_kernel<<<4, 1024>>>(8192, 4096);
    sort_pass_kernel<<<4, 1024>>>(8192, 2048);
    sort_low_kernel<<<4, 1024>>>(8192);

    prep_kernel<<<6, 1024>>>();

    const int nms_smem_bytes = 5 * PRE * 4 + 6016 + POST * 4 + 64;
    cudaFuncSetAttribute(nms_kernel, cudaFuncAttributeMaxDynamicSharedMemorySize, nms_smem_bytes);
    nms_kernel<<<1, 1024, nms_smem_bytes>>>(out);
}

// round 5
// speedup vs baseline: 1.4349x; 1.0716x over previous
#include <cuda_runtime.h>
#include <math.h>
#include <stdint.h>

#define NPOS 2500
#define NPAD 2560
#define NANCH 22500
#define PRE 6000
#define POST 300
#define CAP 8192
#define KSPLIT 6
#define KPART 768          // 4608 / 6
#define LW 188             // 6000 bits -> 188 u32 words

typedef unsigned long long ull;

// ---------------- scratch ----------------
__device__ float g_wt[4608 * 512];              // transposed weights [K][M]
__device__ float g_col[4608 * NPAD];            // im2col matrix [4608][2560]
__device__ float g_part[KSPLIT][512 * NPAD];    // split-K partials
__device__ float g_feat[512 * NPAD];            // conv output (bias+leaky)
__device__ float4 g_boxes[NANCH];
__device__ unsigned int g_key32[NANCH];
__device__ unsigned int g_hist[65536];
__device__ unsigned int g_cut;
__device__ unsigned int g_cnt;
__device__ ull g_sel[CAP];
__device__ float4 g_sbox[PRE];                  // boxes in rank order

// ---------------- f32x2 helpers ----------------
__device__ __forceinline__ void fma2(ull& d, ull a, ull b) {
    asm("fma.rn.f32x2 %0, %1, %2, %0;" : "+l"(d) : "l"(a), "l"(b));
}
__device__ __forceinline__ ull splat2(float x) {
    ull r;
    unsigned u = __float_as_uint(x);
    asm("mov.b64 %0, {%1, %1};" : "=l"(r) : "r"(u));
    return r;
}

// ---------------- zero histogram ----------------
__global__ void zero_hist_kernel() {
    g_hist[blockIdx.x * 256 + threadIdx.x] = 0u;
}

// ---------------- weight transpose: Wt[k][m] = W[m][k] ----------------
__global__ __launch_bounds__(256) void wt_kernel(const float* __restrict__ W) {
    __shared__ float sm[32][33];
    int k0 = blockIdx.x * 32;
    int m0 = blockIdx.y * 32;
    int tx = threadIdx.x & 31;
    int ty = threadIdx.x >> 5;     // 0..7
#pragma unroll
    for (int i = 0; i < 4; i++)
        sm[ty + i * 8][tx] = W[(size_t)(m0 + ty + i * 8) * 4608 + k0 + tx];
    __syncthreads();
#pragma unroll
    for (int i = 0; i < 4; i++)
        g_wt[(size_t)(k0 + ty + i * 8) * 512 + m0 + tx] = sm[tx][ty + i * 8];
}

// ---------------- im2col: g_col[k][n] ----------------
__global__ __launch_bounds__(256) void im2col_kernel(const float* __restrict__ in) {
    int n = blockIdx.x * 256 + threadIdx.x;     // 0..2559
    int k = blockIdx.y;                          // 0..4607
    if (n >= NPAD) return;
    float v = 0.f;
    if (n < NPOS) {
        int ci = k / 9;
        int r = k - ci * 9;
        int kh = r / 3;
        int kw = r - kh * 3;
        int h = n / 50;
        int w = n - h * 50;
        int ih = h + kh - 1;
        int iw = w + kw - 1;
        if (ih >= 0 && ih < 50 && iw >= 0 && iw < 50)
            v = in[ci * NPOS + ih * 50 + iw];
    }
    g_col[(size_t)k * NPAD + n] = v;
}

// ---------------- conv GEMM: split-K, 128x64 tiles, 128 thr, f32x2 (R3 config) ----------------
__global__ __launch_bounds__(128) void conv_gemm_kernel() {
    __shared__ float As[2][16][128];
    __shared__ float Bs[2][16][64];
    const int bn = blockIdx.x * 64;
    const int bm = blockIdx.y * 128;
    const int kb = blockIdx.z * KPART;
    const int t = threadIdx.x;
    const int tm = t >> 3;    // 0..15
    const int tn = t & 7;     // 0..7

    ull acc[8][4];
#pragma unroll
    for (int i = 0; i < 8; i++)
#pragma unroll
        for (int j = 0; j < 4; j++) acc[i][j] = 0ull;

    int akl[4], amc[4];
#pragma unroll
    for (int p = 0; p < 4; p++) {
        int q = t + 128 * p;
        akl[p] = q >> 5;
        amc[p] = (q & 31) * 4;
    }
    int bkl[2], bnc[2];
#pragma unroll
    for (int p = 0; p < 2; p++) {
        int q = t + 128 * p;
        bkl[p] = q >> 4;
        bnc[p] = (q & 15) * 4;
    }

    float4 ar[4], br[2];
#pragma unroll
    for (int p = 0; p < 4; p++)
        ar[p] = *(const float4*)&g_wt[(size_t)(kb + akl[p]) * 512 + bm + amc[p]];
#pragma unroll
    for (int p = 0; p < 2; p++)
        br[p] = *(const float4*)&g_col[(size_t)(kb + bkl[p]) * NPAD + bn + bnc[p]];
#pragma unroll
    for (int p = 0; p < 4; p++)
        *(float4*)&As[0][akl[p]][amc[p]] = ar[p];
#pragma unroll
    for (int p = 0; p < 2; p++)
        *(float4*)&Bs[0][bkl[p]][bnc[p]] = br[p];
    __syncthreads();

    int cur = 0;
    for (int it = 0; it < KPART / 16; it++) {
        int nxt = cur ^ 1;
        bool more = (it + 1) < KPART / 16;
        if (more) {
            int k0 = kb + (it + 1) * 16;
#pragma unroll
            for (int p = 0; p < 4; p++)
                ar[p] = *(const float4*)&g_wt[(size_t)(k0 + akl[p]) * 512 + bm + amc[p]];
#pragma unroll
            for (int p = 0; p < 2; p++)
                br[p] = *(const float4*)&g_col[(size_t)(k0 + bkl[p]) * NPAD + bn + bnc[p]];
        }
#pragma unroll
        for (int kk = 0; kk < 16; kk++) {
            float4 af0 = *(const float4*)&As[cur][kk][tm * 8];
            float4 af1 = *(const float4*)&As[cur][kk][tm * 8 + 4];
            ull bb0 = *(const ull*)&Bs[cur][kk][tn * 8];
            ull bb1 = *(const ull*)&Bs[cur][kk][tn * 8 + 2];
            ull bb2 = *(const ull*)&Bs[cur][kk][tn * 8 + 4];
            ull bb3 = *(const ull*)&Bs[cur][kk][tn * 8 + 6];
            ull aa[8];
            aa[0] = splat2(af0.x); aa[1] = splat2(af0.y);
            aa[2] = splat2(af0.z); aa[3] = splat2(af0.w);
            aa[4] = splat2(af1.x); aa[5] = splat2(af1.y);
            aa[6] = splat2(af1.z); aa[7] = splat2(af1.w);
#pragma unroll
            for (int i = 0; i < 8; i++) {
                fma2(acc[i][0], aa[i], bb0);
                fma2(acc[i][1], aa[i], bb1);
                fma2(acc[i][2], aa[i], bb2);
                fma2(acc[i][3], aa[i], bb3);
            }
        }
        if (more) {
#pragma unroll
            for (int p = 0; p < 4; p++)
                *(float4*)&As[nxt][akl[p]][amc[p]] = ar[p];
#pragma unroll
            for (int p = 0; p < 2; p++)
                *(float4*)&Bs[nxt][bkl[p]][bnc[p]] = br[p];
        }
        __syncthreads();
        cur = nxt;
    }

    float* dst = &g_part[blockIdx.z][(size_t)(bm + tm * 8) * NPAD + bn + tn * 8];
#pragma unroll
    for (int i = 0; i < 8; i++) {
        *(ull*)&dst[(size_t)i * NPAD]     = acc[i][0];
        *(ull*)&dst[(size_t)i * NPAD + 2] = acc[i][1];
        *(ull*)&dst[(size_t)i * NPAD + 4] = acc[i][2];
        *(ull*)&dst[(size_t)i * NPAD + 6] = acc[i][3];
    }
}

// ---------------- reduce split-K + bias + leaky ----------------
__global__ __launch_bounds__(256) void reduce_kernel(const float* __restrict__ bias) {
    int n = blockIdx.x * 256 + threadIdx.x;
    int m = blockIdx.y;
    size_t off = (size_t)m * NPAD + n;
    float v = g_part[0][off];
    v += g_part[1][off];
    v += g_part[2][off];
    v += g_part[3][off];
    v += g_part[4][off];
    v += g_part[5][off];
    v += bias[m];
    g_feat[off] = (v >= 0.f) ? v : 0.01f * v;
}

// ---------------- head GEMM (54x2560x512) fused with decode ----------------
__global__ __launch_bounds__(256) void head_decode_kernel(const float* __restrict__ reg_w,
                                                          const float* __restrict__ cls_w,
                                                          const float* __restrict__ reg_b,
                                                          const float* __restrict__ cls_b) {
    __shared__ float As[16][64];
    __shared__ float Bs[16][64];
    __shared__ float Psm[54][65];
    const int bn = blockIdx.x * 64;
    const int t = threadIdx.x;
    float acc[4][4];
#pragma unroll
    for (int i = 0; i < 4; i++)
#pragma unroll
        for (int j = 0; j < 4; j++) acc[i][j] = 0.f;

    const int tm = t >> 4, tn = t & 15;

    for (int k0 = 0; k0 < 512; k0 += 16) {
        {
            int m = t >> 2;
            int kq = (t & 3) * 4;
            float4 v = make_float4(0.f, 0.f, 0.f, 0.f);
            if (m < 36) v = *(const float4*)&reg_w[m * 512 + k0 + kq];
            else if (m < 54) v = *(const float4*)&cls_w[(m - 36) * 512 + k0 + kq];
            As[kq + 0][m] = v.x;
            As[kq + 1][m] = v.y;
            As[kq + 2][m] = v.z;
            As[kq + 3][m] = v.w;
        }
        {
            int kl = t >> 4;
            int nq = (t & 15) * 4;
            *(float4*)&Bs[kl][nq] = *(const float4*)&g_feat[(size_t)(k0 + kl) * NPAD + bn + nq];
        }
        __syncthreads();
#pragma unroll
        for (int kk = 0; kk < 16; kk++) {
            float a[4], b[4];
            *(float4*)&a[0] = *(float4*)&As[kk][tm * 4];
            *(float4*)&b[0] = *(float4*)&Bs[kk][tn * 4];
#pragma unroll
            for (int i = 0; i < 4; i++)
#pragma unroll
                for (int j = 0; j < 4; j++) acc[i][j] += a[i] * b[j];
        }
        __syncthreads();
    }
#pragma unroll
    for (int i = 0; i < 4; i++) {
        int m = tm * 4 + i;
        if (m < 54)
#pragma unroll
            for (int j = 0; j < 4; j++) Psm[m][tn * 4 + j] = acc[i][j];
    }
    __syncthreads();

    for (int c = t; c < 576; c += 256) {
        int pl = c / 9;
        int a = c - pl * 9;
        int pos = bn + pl;
        if (pos >= NPOS) continue;
        int h = pos / 50;
        int w = pos - h * 50;

        float pr0 = Psm[4 * a + 0][pl] + reg_b[4 * a + 0];
        float pr1 = Psm[4 * a + 1][pl] + reg_b[4 * a + 1];
        float pr2 = Psm[4 * a + 2][pl] + reg_b[4 * a + 2];
        float pr3 = Psm[4 * a + 3][pl] + reg_b[4 * a + 3];
        float l0 = Psm[36 + 2 * a + 0][pl] + cls_b[2 * a + 0];
        float l1 = Psm[36 + 2 * a + 1][pl] + cls_b[2 * a + 1];

        float mx = fmaxf(l0, l1);
        float e0 = expf(l0 - mx);
        float e1 = expf(l1 - mx);
        float score = e1 / (e0 + e1);

        const float rs_[3] = {0.5f, 1.0f, 2.0f};
        const float ss_[3] = {8.0f, 16.0f, 32.0f};
        int ri = a / 3;
        int si = a - ri * 3;
        float hs = (16.0f * ss_[si]) * sqrtf(rs_[ri]);
        float ws = (16.0f * ss_[si]) * sqrtf(1.0f / rs_[ri]);
        float cx = 16.0f * (float)h + 8.0f;
        float cy = 16.0f * (float)w + 8.0f;
        float ax1 = cx - ws * 0.5f;
        float ay1 = cy - hs * 0.5f;

        const float hi = 799.0f;
        float rx1 = fminf(fmaxf(pr0 + ax1, 0.f), hi);
        float ry1 = fminf(fmaxf(pr1 + ay1, 0.f), hi);
        float rx2 = fminf(fmaxf(pr0 + ax1 + pr2 + ws, 0.f), hi);
        float ry2 = fminf(fmaxf(pr1 + ay1 + pr3 + hs, 0.f), hi);

        float wv = pr2 + ws;
        float hv = pr3 + hs;
        bool valid = (wv >= 16.0f) && (hv >= 16.0f);
        float s = valid ? score : -INFINITY;

        int idx = pos * 9 + a;
        g_boxes[idx] = make_float4(rx1, ry1, rx2, ry2);

        unsigned u = __float_as_uint(s);
        u = (u & 0x80000000u) ? ~u : (u | 0x80000000u);
        unsigned du = ~u;
        g_key32[idx] = du;
        atomicAdd(&g_hist[du >> 16], 1u);
    }
}

// ---------------- select cutoff bin ----------------
__global__ __launch_bounds__(1024) void select_kernel() {
    __shared__ unsigned int ps[1024];
    const int t = threadIdx.x;
    unsigned int s = 0;
    int base = t * 64;
#pragma unroll 8
    for (int b = 0; b < 64; b++) s += g_hist[base + b];
    ps[t] = s;
    __syncthreads();
    for (int off = 1; off < 1024; off <<= 1) {
        unsigned int v = (t >= off) ? ps[t - off] : 0u;
        __syncthreads();
        ps[t] += v;
        __syncthreads();
    }
    unsigned int excl = ps[t] - s;
    if (excl < PRE && ps[t] >= PRE) {
        unsigned int c = excl;
        for (int b = 0; b < 64; b++) {
            c += g_hist[base + b];
            if (c >= PRE) { g_cut = (unsigned)(base + b); break; }
        }
    }
    if (t == 0) g_cnt = 0u;
    for (int i = t; i < CAP; i += 1024) g_sel[i] = 0xFFFFFFFFFFFFFFFFull;
}

// ---------------- compact ----------------
__global__ __launch_bounds__(256) void compact_kernel() {
    int i = blockIdx.x * 256 + threadIdx.x;
    if (i >= NANCH) return;
    unsigned int k = g_key32[i];
    if ((k >> 16) <= g_cut) {
        unsigned int p = atomicAdd(&g_cnt, 1u);
        if (p < CAP) g_sel[p] = ((ull)k << 32) | (unsigned)i;
    }
}

// ---------------- bitonic sort (multi-block, 8192 keys) ----------------
__device__ __forceinline__ void cmpswap_u64(ull* a, ull* b, bool up) {
    ull x = *a, y = *b;
    bool sw = up ? (x > y) : (x < y);
    if (sw) { *a = y; *b = x; }
}

__global__ __launch_bounds__(1024) void sort_local_kernel() {
    __shared__ ull s[2048];
    int base = blockIdx.x * 2048;
    int t = threadIdx.x;
    s[t] = g_sel[base + t];
    s[t + 1024] = g_sel[base + t + 1024];
    __syncthreads();
    for (int k = 2; k <= 2048; k <<= 1) {
        for (int j = k >> 1; j > 0; j >>= 1) {
            int i = ((t & ~(j - 1)) << 1) | (t & (j - 1));
            int p = i | j;
            bool up = (((base + i) & k) == 0);
            cmpswap_u64(&s[i], &s[p], up);
            __syncthreads();
        }
    }
    g_sel[base + t] = s[t];
    g_sel[base + t + 1024] = s[t + 1024];
}

__global__ __launch_bounds__(1024) void sort_pass_kernel(int k, int j) {
    int t = blockIdx.x * 1024 + threadIdx.x;
    int i = ((t & ~(j - 1)) << 1) | (t & (j - 1));
    int p = i + j;
    bool up = ((i & k) == 0);
    ull a = g_sel[i], b = g_sel[p];
    bool sw = up ? (a > b) : (a < b);
    if (sw) { g_sel[i] = b; g_sel[p] = a; }
}

__global__ __launch_bounds__(1024) void sort_low_kernel(int k) {
    __shared__ ull s[2048];
    int base = blockIdx.x * 2048;
    int t = threadIdx.x;
    s[t] = g_sel[base + t];
    s[t + 1024] = g_sel[base + t + 1024];
    __syncthreads();
    for (int j = 1024; j > 0; j >>= 1) {
        int i = ((t & ~(j - 1)) << 1) | (t & (j - 1));
        int p = i | j;
        bool up = (((base + i) & k) == 0);
        cmpswap_u64(&s[i], &s[p], up);
        __syncthreads();
    }
    g_sel[base + t] = s[t];
    g_sel[base + t + 1024] = s[t + 1024];
}

// ---------------- prep: boxes in rank order ----------------
__global__ void prep_kernel() {
    int r = blockIdx.x * 1024 + threadIdx.x;
    if (r < PRE) {
        int idx = (int)(g_sel[r] & 0xFFFFFFFFull);
        g_sbox[r] = g_boxes[idx];
    }
}

// ---------------- NMS: single block, live-word skipping ----------------
extern __shared__ float nsm[];
__global__ __launch_bounds__(1024) void nms_kernel(float* __restrict__ out) {
    float* X1 = nsm;
    float* Y1 = X1 + PRE;
    float* X2 = Y1 + PRE;
    float* Y2 = X2 + PRE;
    float* AR = Y2 + PRE;
    int* sel = (int*)(AR + PRE);                 // POST ints
    __shared__ unsigned live[LW];
    __shared__ unsigned kf[LW];
    __shared__ int s_cur, s_nsel, s_wpos;
    const int t = threadIdx.x;
    const int lane = t & 31;
    const int wid = t >> 5;

    for (int r = t; r < PRE; r += 1024) {
        float4 b = g_sbox[r];
        X1[r] = b.x; Y1[r] = b.y; X2[r] = b.z; Y2[r] = b.w;
        AR[r] = (b.z - b.x + 1.0f) * (b.w - b.y + 1.0f);
    }
    if (t < LW) {
        live[t] = (t == LW - 1) ? 0x0000FFFFu : 0xFFFFFFFFu;  // 187*32+16 = 6000
        kf[t] = 0u;
    }
    if (t == 0) { s_nsel = 0; s_wpos = 0; }
    __syncthreads();

    while (true) {
        if (t == 0) {
            if (s_nsel >= POST) {
                s_cur = -1;
            } else {
                int w = s_wpos;
                unsigned word = 0;
                while (w < LW && (word = live[w]) == 0u) w++;
                s_wpos = w;
                if (w == LW) {
                    s_cur = -1;
                } else {
                    int b = __ffs(word) - 1;
                    int cur = w * 32 + b;
                    live[w] = word & ~(1u << b);
                    kf[w] |= 1u << b;
                    sel[s_nsel++] = cur;
                    s_cur = cur;
                }
            }
        }
        __syncthreads();
        int cur = s_cur;
        if (cur < 0) break;

        float x1i = X1[cur], y1i = Y1[cur], x2i = X2[cur], y2i = Y2[cur], ai = AR[cur];
        int w0 = (cur + 1) >> 5;
        int off = (cur + 1) & 31;
        for (int w = w0 + wid; w < LW; w += 32) {
            unsigned wv = live[w];
            if (w == w0) wv &= 0xFFFFFFFFu << off;
            if (wv == 0u) continue;
            bool supp = false;
            if ((wv >> lane) & 1u) {
                int j = w * 32 + lane;
                float xx1 = fmaxf(x1i, X1[j]);
                float yy1 = fmaxf(y1i, Y1[j]);
                float xx2 = fminf(x2i, X2[j]);
                float yy2 = fmaxf(y2i, Y2[j]);   // reference's maximum bug preserved
                float ww = fmaxf(0.f, xx2 - xx1 + 1.0f);
                float hh = fmaxf(0.f, yy2 - yy1 + 1.0f);
                float inter = ww * hh;
                float ov = inter / (ai + AR[j] - inter);
                supp = (ov > 0.7f);
            }
            unsigned m = __ballot_sync(0xFFFFFFFFu, supp);
            if (lane == 0 && m) atomicAnd(&live[w], ~m);
        }
        __syncthreads();
    }

    // pad with suppressed (ascending rank): suppressed = ~live & ~kf (valid bits only)
    if (t == 0 && s_nsel < POST) {
        int c = s_nsel;
        for (int w = 0; w < LW && c < POST; w++) {
            unsigned valid = (w == LW - 1) ? 0x0000FFFFu : 0xFFFFFFFFu;
            unsigned word = ~live[w] & ~kf[w] & valid;
            while (word && c < POST) {
                int b = __ffs(word) - 1;
                sel[c++] = w * 32 + b;
                word &= word - 1;
            }
        }
        s_nsel = c;
    }
    __syncthreads();

    if (t < POST) {
        int rk = sel[t];
        out[t * 4 + 0] = X1[rk];
        out[t * 4 + 1] = Y1[rk];
        out[t * 4 + 2] = X2[rk] - X1[rk] + 1.0f;
        out[t * 4 + 3] = Y2[rk] - Y1[rk] + 1.0f;
    }
}

// ---------------- launch ----------------
extern "C" void kernel_launch(void* const* d_in, const int* in_sizes, int n_in,
                              void* d_out, int out_size) {
    const float* in_features = (const float*)d_in[0];
    const float* conv_w = (const float*)d_in[1];
    const float* conv_b = (const float*)d_in[2];
    const float* reg_w = (const float*)d_in[3];
    const float* reg_b = (const float*)d_in[4];
    const float* cls_w = (const float*)d_in[5];
    const float* cls_b = (const float*)d_in[6];
    float* out = (float*)d_out;

    const float* in7 = in_features + (size_t)7 * 512 * NPOS;  // only batch -1 consumed

    zero_hist_kernel<<<256, 256>>>();
    wt_kernel<<<dim3(144, 16), 256>>>(conv_w);
    im2col_kernel<<<dim3(10, 4608), 256>>>(in7);
    conv_gemm_kernel<<<dim3(40, 4, KSPLIT), 128>>>();
    reduce_kernel<<<dim3(10, 512), 256>>>(conv_b);
    head_decode_kernel<<<40, 256>>>(reg_w, cls_w, reg_b, cls_b);
    select_kernel<<<1, 1024>>>();
    compact_kernel<<<88, 256>>>();

    sort_local_kernel<<<4, 1024>>>();
    sort_pass_kernel<<<4, 1024>>>(4096, 2048);
    sort_low_kernel<<<4, 1024>>>(4096);
    sort_pass_kernel<<<4, 1024>>>(8192, 4096);
    sort_pass_kernel<<<4, 1024>>>(8192, 2048);
    sort_low_kernel<<<4, 1024>>>(8192);

    prep_kernel<<<6, 1024>>>();

    const int nms_smem_bytes = 5 * PRE * 4 + POST * 4 + 64;
    cudaFuncSetAttribute(nms_kernel, cudaFuncAttributeMaxDynamicSharedMemorySize, nms_smem_bytes);
    nms_kernel<<<1, 1024, nms_smem_bytes>>>(out);
}